// round 4
// baseline (speedup 1.0000x reference)
#include <cuda_runtime.h>

// Problem constants (fixed by the reference)
#define BSZ   2
#define LEN   2048
#define DQ    512
#define SQ    4
#define SH    2                  // s-lanes per thread in K1 (SQ/2)
#define NC    128                // number of chunks along L
#define CHUNK (LEN / NC)         // 16 steps per chunk
#define EPSQ  1e-6f

// Scratch: chunk summaries and carries, laid out [b][chunk][s][d].
__device__ float4 g_Q  [BSZ * NC * SQ * DQ];
__device__ float4 g_H  [BSZ * NC * SQ * DQ];
__device__ float4 g_Hin[BSZ * NC * SQ * DQ];

// ---------------------------------------------------------------------------
// Quaternion helpers
// ---------------------------------------------------------------------------
__device__ __forceinline__ float4 qmuladd(const float4 a, const float4 b, const float4 c) {
    float4 r;
    r.x = fmaf(a.x, b.x, fmaf(-a.y, b.y, fmaf(-a.z, b.z, fmaf(-a.w, b.w, c.x))));
    r.y = fmaf(a.x, b.y, fmaf( a.y, b.x, fmaf( a.z, b.w, fmaf(-a.w, b.z, c.y))));
    r.z = fmaf(a.x, b.z, fmaf(-a.y, b.w, fmaf( a.z, b.x, fmaf( a.w, b.y, c.z))));
    r.w = fmaf(a.x, b.w, fmaf( a.y, b.z, fmaf(-a.z, b.y, fmaf( a.w, b.x, c.w))));
    return r;
}
__device__ __forceinline__ float4 qmul(const float4 a, const float4 b) {
    return qmuladd(a, b, make_float4(0.f, 0.f, 0.f, 0.f));
}

__device__ __forceinline__ float frcp_fast(float x) {
    float r;
    asm("rcp.approx.f32 %0, %1;" : "=f"(r) : "f"(x));
    return r * (2.0f - x * r);
}

// Per-step transition quaternion:
//   w  = dtv * ah                (ah = 0.5*A)
//   n2 = (1-w_r)^2 + |w_v|^2 + eps ; r2 = 2/n2
//   q  = (omr*r2 - 1, w_i*r2, w_j*r2, w_k*r2)
// Injection identity (g = den_inv*dt = (dt/2)(q + ident)):
//   us  = u*(dt/2)   [shared across s]
//   Bu0 = B (x) us ; Bu = q (x) Bu0 + Bu0
__device__ __forceinline__ float4 step_q(const float dtv, const float4 ah) {
    const float wr = dtv * ah.x, wi = dtv * ah.y, wj = dtv * ah.z, wk = dtv * ah.w;
    const float omr = 1.0f - wr;
    const float vve = fmaf(wi, wi, fmaf(wj, wj, fmaf(wk, wk, EPSQ)));
    const float n2  = fmaf(omr, omr, vve);
    const float rinv = frcp_fast(n2);
    const float r2 = rinv + rinv;
    return make_float4(fmaf(omr, r2, -1.0f), wi * r2, wj * r2, wk * r2);
}

// ---------------------------------------------------------------------------
// K1: per-(b, chunk, d, s-half) thread — chunk transforms (Q_total, H_total)
//     lane bits [0:4) = d low 4 bits, bit 4 = s-half (B loads warp-shared).
// ---------------------------------------------------------------------------
__global__ void __launch_bounds__(256)
k_summary(const float* __restrict__ u, const float* __restrict__ dt,
          const float* __restrict__ Bin,
          const float* __restrict__ A_log, const float* __restrict__ A_i,
          const float* __restrict__ A_j,  const float* __restrict__ A_k)
{
    const int gt = blockIdx.x * blockDim.x + threadIdx.x;
    const int lane16 = gt & 15;
    const int hbit = (gt >> 4) & 1;
    const int rest = gt >> 5;
    const int d = ((rest & 31) << 4) + lane16;     // DQ/16 = 32
    const int c = (rest >> 5) & (NC - 1);
    const int b = rest >> 12;
    const int s0 = hbit * SH;

    float4 ah[SH];
#pragma unroll
    for (int s = 0; s < SH; s++) {
        const int ai = d * SQ + s0 + s;
        ah[s] = make_float4(-0.5f * expf(A_log[ai]), 0.5f * A_i[ai],
                             0.5f * A_j[ai],          0.5f * A_k[ai]);
    }

    const float4* __restrict__ u4 = (const float4*)u;
    const float4* __restrict__ B4 = (const float4*)Bin;

    const int t0 = c * CHUNK;
    float4 Q[SH], H[SH];

    // Peel first iteration: Q = q, H = Bu.
    {
        const int td = b * LEN + t0;
        const float  dtv = dt[td * DQ + d];
        const float4 uu  = u4[td * DQ + d];
        const float  hdt = 0.5f * dtv;
        const float4 us  = make_float4(uu.x * hdt, uu.y * hdt, uu.z * hdt, uu.w * hdt);
#pragma unroll
        for (int s = 0; s < SH; s++) {
            const float4 Bq = B4[td * SQ + s0 + s];
            const float4 q  = step_q(dtv, ah[s]);
            const float4 Bu0 = qmul(Bq, us);
            Q[s] = q;
            H[s] = qmuladd(q, Bu0, Bu0);
        }
    }

#pragma unroll 2
    for (int i = 1; i < CHUNK; i++) {
        const int td = b * LEN + t0 + i;
        const float  dtv = dt[td * DQ + d];
        const float4 uu  = u4[td * DQ + d];
        const float  hdt = 0.5f * dtv;
        const float4 us  = make_float4(uu.x * hdt, uu.y * hdt, uu.z * hdt, uu.w * hdt);
#pragma unroll
        for (int s = 0; s < SH; s++) {
            const float4 Bq = B4[td * SQ + s0 + s];
            const float4 q  = step_q(dtv, ah[s]);
            const float4 Bu0 = qmul(Bq, us);
            const float4 Bu  = qmuladd(q, Bu0, Bu0);
            H[s] = qmuladd(q, H[s], Bu);
            Q[s] = qmul(q, Q[s]);
        }
    }

#pragma unroll
    for (int s = 0; s < SH; s++) {
        const int idx = ((b * NC + c) * SQ + s0 + s) * DQ + d;
        g_Q[idx] = Q[s];
        g_H[idx] = H[s];
    }
}

// ---------------------------------------------------------------------------
// K2: per-(b, s, d) thread — sequential scan over NC chunk transforms.
// ---------------------------------------------------------------------------
__global__ void __launch_bounds__(256)
k_carry()
{
    const int tid = blockIdx.x * blockDim.x + threadIdx.x;
    const int d = tid % DQ;
    const int s = (tid / DQ) % SQ;
    const int b = tid / (DQ * SQ);
    if (b >= BSZ) return;

    float4 carry = make_float4(0.f, 0.f, 0.f, 0.f);
#pragma unroll 4
    for (int c = 0; c < NC; c++) {
        const int idx = ((b * NC + c) * SQ + s) * DQ + d;
        g_Hin[idx] = carry;
        carry = qmuladd(g_Q[idx], carry, g_H[idx]);
    }
}

// ---------------------------------------------------------------------------
// K3: per-(b, chunk, d) thread — all 4 s-lanes in-thread, recompute with
//     carry, sum y in registers, full-width float4 store.
//     B/C loads are warp-uniform (lanes share td) -> broadcast.
// ---------------------------------------------------------------------------
__global__ void __launch_bounds__(256)
k_final(const float* __restrict__ u, const float* __restrict__ dt,
        const float* __restrict__ Bin, const float* __restrict__ Cin,
        const float* __restrict__ A_log, const float* __restrict__ A_i,
        const float* __restrict__ A_j,  const float* __restrict__ A_k,
        float* __restrict__ out)
{
    const int gt = blockIdx.x * blockDim.x + threadIdx.x;
    const int d = gt & (DQ - 1);
    const int c = (gt >> 9) & (NC - 1);
    const int b = gt >> (9 + 7);

    float4 ah[SQ];
#pragma unroll
    for (int s = 0; s < SQ; s++) {
        const int ai = d * SQ + s;
        ah[s] = make_float4(-0.5f * expf(A_log[ai]), 0.5f * A_i[ai],
                             0.5f * A_j[ai],          0.5f * A_k[ai]);
    }

    float4 h[SQ];
#pragma unroll
    for (int s = 0; s < SQ; s++)
        h[s] = g_Hin[((b * NC + c) * SQ + s) * DQ + d];

    const float4* __restrict__ u4 = (const float4*)u;
    const float4* __restrict__ B4 = (const float4*)Bin;
    const float4* __restrict__ C4 = (const float4*)Cin;
    float4* __restrict__ o4 = (float4*)out;

    const int t0 = c * CHUNK;
#pragma unroll 2
    for (int i = 0; i < CHUNK; i++) {
        const int td = b * LEN + t0 + i;
        const float  dtv = dt[td * DQ + d];
        const float4 uu  = u4[td * DQ + d];
        const float  hdt = 0.5f * dtv;
        const float4 us  = make_float4(uu.x * hdt, uu.y * hdt, uu.z * hdt, uu.w * hdt);
        float4 y = make_float4(0.f, 0.f, 0.f, 0.f);
#pragma unroll
        for (int s = 0; s < SQ; s++) {
            const float4 Bq = B4[td * SQ + s];
            const float4 Cq = C4[td * SQ + s];
            const float4 q  = step_q(dtv, ah[s]);
            const float4 Bu0 = qmul(Bq, us);
            const float4 Bu  = qmuladd(q, Bu0, Bu0);
            h[s] = qmuladd(q, h[s], Bu);
            y = qmuladd(Cq, h[s], y);
        }
        o4[td * DQ + d] = y;
    }
}

// ---------------------------------------------------------------------------
// Launch
// ---------------------------------------------------------------------------
extern "C" void kernel_launch(void* const* d_in, const int* in_sizes, int n_in,
                              void* d_out, int out_size)
{
    const float* u     = (const float*)d_in[0];
    const float* dt    = (const float*)d_in[1];
    const float* Bin   = (const float*)d_in[2];
    const float* Cin   = (const float*)d_in[3];
    const float* A_log = (const float*)d_in[4];
    const float* A_i   = (const float*)d_in[5];
    const float* A_j   = (const float*)d_in[6];
    const float* A_k   = (const float*)d_in[7];
    float* out = (float*)d_out;

    const int k1_threads = BSZ * NC * DQ * 2;   // 262144 (s split in halves)
    const int k2_threads = BSZ * SQ * DQ;       // 4096
    const int k3_threads = BSZ * NC * DQ;       // 131072 (all s in-thread)

    k_summary<<<k1_threads / 256, 256>>>(u, dt, Bin, A_log, A_i, A_j, A_k);
    k_carry<<<(k2_threads + 255) / 256, 256>>>();
    k_final<<<k3_threads / 256, 256>>>(u, dt, Bin, Cin, A_log, A_i, A_j, A_k, out);
}

// round 5
// speedup vs baseline: 1.3070x; 1.3070x over previous
#include <cuda_runtime.h>

// Problem constants (fixed by the reference)
#define BSZ    2
#define LEN    2048
#define DQ     512
#define SQ     4
#define SH     2                 // s-lanes per thread in K1
#define NC     128               // fine chunks along L (K1/K2 granularity)
#define CHUNKF (LEN / NC)        // 16 steps per fine chunk
#define NC3    64                // coarse chunks for K3
#define CHUNK3 (LEN / NC3)       // 32 steps per K3 chunk
#define NCL    (NC / 32)         // fine chunks per lane in K2 warp scan (4)
#define EPSQ   1e-6f

// Scratch: chunk summaries and carries, laid out [b][chunk][s][d].
__device__ float4 g_Q  [BSZ * NC * SQ * DQ];
__device__ float4 g_H  [BSZ * NC * SQ * DQ];
__device__ float4 g_Hin[BSZ * NC * SQ * DQ];

// ---------------------------------------------------------------------------
// Quaternion helpers
// ---------------------------------------------------------------------------
__device__ __forceinline__ float4 qmuladd(const float4 a, const float4 b, const float4 c) {
    float4 r;
    r.x = fmaf(a.x, b.x, fmaf(-a.y, b.y, fmaf(-a.z, b.z, fmaf(-a.w, b.w, c.x))));
    r.y = fmaf(a.x, b.y, fmaf( a.y, b.x, fmaf( a.z, b.w, fmaf(-a.w, b.z, c.y))));
    r.z = fmaf(a.x, b.z, fmaf(-a.y, b.w, fmaf( a.z, b.x, fmaf( a.w, b.y, c.z))));
    r.w = fmaf(a.x, b.w, fmaf( a.y, b.z, fmaf(-a.z, b.y, fmaf( a.w, b.x, c.w))));
    return r;
}
__device__ __forceinline__ float4 qmul(const float4 a, const float4 b) {
    return qmuladd(a, b, make_float4(0.f, 0.f, 0.f, 0.f));
}

__device__ __forceinline__ float frcp_fast(float x) {
    float r;
    asm("rcp.approx.f32 %0, %1;" : "=f"(r) : "f"(x));
    return r * (2.0f - x * r);
}

// Per-step transition quaternion (ah = 0.5*A):
//   n2 = (1-w_r)^2 + |w_v|^2 + eps ; r2 = 2/n2
//   q  = (omr*r2 - 1, w_i*r2, w_j*r2, w_k*r2)
// Injection identity:  us = u*(dt/2);  Bu0 = B (x) us;  Bu = q (x) Bu0 + Bu0
__device__ __forceinline__ float4 step_q(const float dtv, const float4 ah) {
    const float wr = dtv * ah.x, wi = dtv * ah.y, wj = dtv * ah.z, wk = dtv * ah.w;
    const float omr = 1.0f - wr;
    const float vve = fmaf(wi, wi, fmaf(wj, wj, fmaf(wk, wk, EPSQ)));
    const float n2  = fmaf(omr, omr, vve);
    const float rinv = frcp_fast(n2);
    const float r2 = rinv + rinv;
    return make_float4(fmaf(omr, r2, -1.0f), wi * r2, wj * r2, wk * r2);
}

__device__ __forceinline__ float4 shfl_up4(const float4 v, int off) {
    float4 r;
    r.x = __shfl_up_sync(0xffffffffu, v.x, off);
    r.y = __shfl_up_sync(0xffffffffu, v.y, off);
    r.z = __shfl_up_sync(0xffffffffu, v.z, off);
    r.w = __shfl_up_sync(0xffffffffu, v.w, off);
    return r;
}

// ---------------------------------------------------------------------------
// K1: per-(b, fine-chunk, d, s-half) thread — chunk transforms (Q, H).
// ---------------------------------------------------------------------------
__global__ void __launch_bounds__(256)
k_summary(const float* __restrict__ u, const float* __restrict__ dt,
          const float* __restrict__ Bin,
          const float* __restrict__ A_log, const float* __restrict__ A_i,
          const float* __restrict__ A_j,  const float* __restrict__ A_k)
{
    const int gt = blockIdx.x * blockDim.x + threadIdx.x;
    const int lane16 = gt & 15;
    const int hbit = (gt >> 4) & 1;
    const int rest = gt >> 5;
    const int d = ((rest & 31) << 4) + lane16;
    const int c = (rest >> 5) & (NC - 1);
    const int b = rest >> 12;
    const int s0 = hbit * SH;

    float4 ah[SH];
#pragma unroll
    for (int s = 0; s < SH; s++) {
        const int ai = d * SQ + s0 + s;
        ah[s] = make_float4(-0.5f * __expf(A_log[ai]), 0.5f * A_i[ai],
                             0.5f * A_j[ai],           0.5f * A_k[ai]);
    }

    const float4* __restrict__ u4 = (const float4*)u;
    const float4* __restrict__ B4 = (const float4*)Bin;

    const int t0 = c * CHUNKF;
    float4 Q[SH], H[SH];

    {   // peel first step: Q = q, H = Bu
        const int td = b * LEN + t0;
        const float  dtv = dt[td * DQ + d];
        const float4 uu  = u4[td * DQ + d];
        const float  hdt = 0.5f * dtv;
        const float4 us  = make_float4(uu.x * hdt, uu.y * hdt, uu.z * hdt, uu.w * hdt);
#pragma unroll
        for (int s = 0; s < SH; s++) {
            const float4 Bq = B4[td * SQ + s0 + s];
            const float4 q  = step_q(dtv, ah[s]);
            const float4 Bu0 = qmul(Bq, us);
            Q[s] = q;
            H[s] = qmuladd(q, Bu0, Bu0);
        }
    }

#pragma unroll 2
    for (int i = 1; i < CHUNKF; i++) {
        const int td = b * LEN + t0 + i;
        const float  dtv = dt[td * DQ + d];
        const float4 uu  = u4[td * DQ + d];
        const float  hdt = 0.5f * dtv;
        const float4 us  = make_float4(uu.x * hdt, uu.y * hdt, uu.z * hdt, uu.w * hdt);
#pragma unroll
        for (int s = 0; s < SH; s++) {
            const float4 Bq = B4[td * SQ + s0 + s];
            const float4 q  = step_q(dtv, ah[s]);
            const float4 Bu0 = qmul(Bq, us);
            const float4 Bu  = qmuladd(q, Bu0, Bu0);
            H[s] = qmuladd(q, H[s], Bu);
            Q[s] = qmul(q, Q[s]);
        }
    }

#pragma unroll
    for (int s = 0; s < SH; s++) {
        const int idx = ((b * NC + c) * SQ + s0 + s) * DQ + d;
        g_Q[idx] = Q[s];
        g_H[idx] = H[s];
    }
}

// ---------------------------------------------------------------------------
// K2: warp-parallel affine scan. One warp per (b,s,d) chain; each lane owns
//     NCL=4 consecutive fine chunks. Local compose -> 5-round shfl_up scan
//     of the affine pair (Q,H) -> exclusive shift -> replay to emit Hin.
// ---------------------------------------------------------------------------
__global__ void __launch_bounds__(256)
k_carry()
{
    const int gt = blockIdx.x * blockDim.x + threadIdx.x;
    const int lane = gt & 31;
    const int w = gt >> 5;                 // chain id in [0, BSZ*SQ*DQ)
    const int d = w & (DQ - 1);
    const int s = (w >> 9) & (SQ - 1);
    const int b = w >> 11;

    const int cstride = SQ * DQ;
    const int base = (b * NC * SQ + s) * DQ + d;
    const int c0 = lane * NCL;

    float4 Qc[NCL], Hc[NCL];
#pragma unroll
    for (int j = 0; j < NCL; j++) {
        const int idx = base + (c0 + j) * cstride;
        Qc[j] = g_Q[idx];
        Hc[j] = g_H[idx];
    }

    // Local inclusive composition over this lane's 4 chunks.
    float4 Qs = Qc[0], Hs = Hc[0];
#pragma unroll
    for (int j = 1; j < NCL; j++) {
        Hs = qmuladd(Qc[j], Hs, Hc[j]);
        Qs = qmul(Qc[j], Qs);
    }

    // Warp inclusive scan: combine earlier-prefix (Qp,Hp) from lane-off.
#pragma unroll
    for (int off = 1; off < 32; off <<= 1) {
        const float4 Qp = shfl_up4(Qs, off);
        const float4 Hp = shfl_up4(Hs, off);
        if (lane >= off) {
            Hs = qmuladd(Qs, Hp, Hs);   // uses pre-update Qs (current segment)
            Qs = qmul(Qs, Qp);
        }
    }

    // Exclusive prefix state = inclusive of lane-1 (identity for lane 0).
    float4 h = shfl_up4(Hs, 1);
    if (lane == 0) h = make_float4(0.f, 0.f, 0.f, 0.f);

    // Replay: emit carry-in for each owned chunk.
#pragma unroll
    for (int j = 0; j < NCL; j++) {
        const int idx = base + (c0 + j) * cstride;
        g_Hin[idx] = h;
        h = qmuladd(Qc[j], h, Hc[j]);
    }
}

// ---------------------------------------------------------------------------
// K3: per-(b, coarse-chunk, d) thread — all 4 s-lanes in-thread, recompute
//     with carry (Hin at fine chunk 2c), sum y in registers, float4 store.
// ---------------------------------------------------------------------------
__global__ void __launch_bounds__(256)
k_final(const float* __restrict__ u, const float* __restrict__ dt,
        const float* __restrict__ Bin, const float* __restrict__ Cin,
        const float* __restrict__ A_log, const float* __restrict__ A_i,
        const float* __restrict__ A_j,  const float* __restrict__ A_k,
        float* __restrict__ out)
{
    const int gt = blockIdx.x * blockDim.x + threadIdx.x;
    const int d = gt & (DQ - 1);
    const int c = (gt >> 9) & (NC3 - 1);
    const int b = gt >> 15;

    float4 ah[SQ];
#pragma unroll
    for (int s = 0; s < SQ; s++) {
        const int ai = d * SQ + s;
        ah[s] = make_float4(-0.5f * __expf(A_log[ai]), 0.5f * A_i[ai],
                             0.5f * A_j[ai],           0.5f * A_k[ai]);
    }

    float4 h[SQ];
#pragma unroll
    for (int s = 0; s < SQ; s++)
        h[s] = g_Hin[((b * NC + 2 * c) * SQ + s) * DQ + d];

    const float4* __restrict__ u4 = (const float4*)u;
    const float4* __restrict__ B4 = (const float4*)Bin;
    const float4* __restrict__ C4 = (const float4*)Cin;
    float4* __restrict__ o4 = (float4*)out;

    const int t0 = c * CHUNK3;
#pragma unroll 2
    for (int i = 0; i < CHUNK3; i++) {
        const int td = b * LEN + t0 + i;
        const float  dtv = dt[td * DQ + d];
        const float4 uu  = u4[td * DQ + d];
        const float  hdt = 0.5f * dtv;
        const float4 us  = make_float4(uu.x * hdt, uu.y * hdt, uu.z * hdt, uu.w * hdt);
        float4 y = make_float4(0.f, 0.f, 0.f, 0.f);
#pragma unroll
        for (int s = 0; s < SQ; s++) {
            const float4 Bq = B4[td * SQ + s];
            const float4 Cq = C4[td * SQ + s];
            const float4 q  = step_q(dtv, ah[s]);
            const float4 Bu0 = qmul(Bq, us);
            const float4 Bu  = qmuladd(q, Bu0, Bu0);
            h[s] = qmuladd(q, h[s], Bu);
            y = qmuladd(Cq, h[s], y);
        }
        o4[td * DQ + d] = y;
    }
}

// ---------------------------------------------------------------------------
// Launch
// ---------------------------------------------------------------------------
extern "C" void kernel_launch(void* const* d_in, const int* in_sizes, int n_in,
                              void* d_out, int out_size)
{
    const float* u     = (const float*)d_in[0];
    const float* dt    = (const float*)d_in[1];
    const float* Bin   = (const float*)d_in[2];
    const float* Cin   = (const float*)d_in[3];
    const float* A_log = (const float*)d_in[4];
    const float* A_i   = (const float*)d_in[5];
    const float* A_j   = (const float*)d_in[6];
    const float* A_k   = (const float*)d_in[7];
    float* out = (float*)d_out;

    const int k1_threads = BSZ * NC * DQ * 2;       // 262144
    const int k2_threads = BSZ * SQ * DQ * 32;      // 131072 (warp per chain)
    const int k3_threads = BSZ * NC3 * DQ;          // 65536

    k_summary<<<k1_threads / 256, 256>>>(u, dt, Bin, A_log, A_i, A_j, A_k);
    k_carry<<<k2_threads / 256, 256>>>();
    k_final<<<k3_threads / 256, 256>>>(u, dt, Bin, Cin, A_log, A_i, A_j, A_k, out);
}

// round 6
// speedup vs baseline: 1.3800x; 1.0559x over previous
#include <cuda_runtime.h>

// Problem constants (fixed by the reference)
#define BSZ    2
#define LEN    2048
#define DQ     512
#define SQ     4
#define SH     2                 // s-lanes per thread in K1
#define NC     128               // fine chunks along L (K1/K2 granularity)
#define CHUNKF (LEN / NC)        // 16 steps per fine chunk
#define NC3    64                // coarse chunks for K3
#define CHUNK3 (LEN / NC3)       // 32 steps per K3 chunk
#define NCL    (NC / 32)         // fine chunks per lane in K2 warp scan (4)
#define EPSQ   1e-6f

// Scratch: chunk summaries and carries, laid out [b][chunk][s][d].
__device__ float4 g_Q  [BSZ * NC * SQ * DQ];
__device__ float4 g_H  [BSZ * NC * SQ * DQ];
__device__ float4 g_Hin[BSZ * NC * SQ * DQ];

// ---------------------------------------------------------------------------
// Quaternion helpers
// ---------------------------------------------------------------------------
__device__ __forceinline__ float4 qmuladd(const float4 a, const float4 b, const float4 c) {
    float4 r;
    r.x = fmaf(a.x, b.x, fmaf(-a.y, b.y, fmaf(-a.z, b.z, fmaf(-a.w, b.w, c.x))));
    r.y = fmaf(a.x, b.y, fmaf( a.y, b.x, fmaf( a.z, b.w, fmaf(-a.w, b.z, c.y))));
    r.z = fmaf(a.x, b.z, fmaf(-a.y, b.w, fmaf( a.z, b.x, fmaf( a.w, b.y, c.z))));
    r.w = fmaf(a.x, b.w, fmaf( a.y, b.z, fmaf(-a.z, b.y, fmaf( a.w, b.x, c.w))));
    return r;
}
__device__ __forceinline__ float4 qmul(const float4 a, const float4 b) {
    return qmuladd(a, b, make_float4(0.f, 0.f, 0.f, 0.f));
}
__device__ __forceinline__ float4 add4(const float4 a, const float4 b) {
    return make_float4(a.x + b.x, a.y + b.y, a.z + b.z, a.w + b.w);
}

// Approximate reciprocal (no Newton step): rel err ~2.4e-7, fine vs 1e-3 tol.
__device__ __forceinline__ float frcp(float x) {
    float r;
    asm("rcp.approx.f32 %0, %1;" : "=f"(r) : "f"(x));
    return r;
}

// Per-step transition quaternion (ah = 0.5*A):
//   n2 = (1-w_r)^2 + |w_v|^2 + eps ; r2 = 2/n2
//   q  = (omr*r2 - 1, w_i*r2, w_j*r2, w_k*r2)
// Injection identity:  us = u*(dt/2);  Bu0 = B (x) us
// Merged state update: h' = q (x) (h + Bu0) + Bu0
__device__ __forceinline__ float4 step_q(const float dtv, const float4 ah) {
    const float wr = dtv * ah.x, wi = dtv * ah.y, wj = dtv * ah.z, wk = dtv * ah.w;
    const float omr = 1.0f - wr;
    const float vve = fmaf(wi, wi, fmaf(wj, wj, fmaf(wk, wk, EPSQ)));
    const float n2  = fmaf(omr, omr, vve);
    const float r2  = frcp(n2) * 2.0f;
    return make_float4(fmaf(omr, r2, -1.0f), wi * r2, wj * r2, wk * r2);
}

__device__ __forceinline__ float4 shfl_up4(const float4 v, int off) {
    float4 r;
    r.x = __shfl_up_sync(0xffffffffu, v.x, off);
    r.y = __shfl_up_sync(0xffffffffu, v.y, off);
    r.z = __shfl_up_sync(0xffffffffu, v.z, off);
    r.w = __shfl_up_sync(0xffffffffu, v.w, off);
    return r;
}

// ---------------------------------------------------------------------------
// K1: per-(b, fine-chunk, d, s-half) thread — chunk transforms (Q, H).
// ---------------------------------------------------------------------------
__global__ void __launch_bounds__(256)
k_summary(const float* __restrict__ u, const float* __restrict__ dt,
          const float* __restrict__ Bin,
          const float* __restrict__ A_log, const float* __restrict__ A_i,
          const float* __restrict__ A_j,  const float* __restrict__ A_k)
{
    const int gt = blockIdx.x * blockDim.x + threadIdx.x;
    const int lane16 = gt & 15;
    const int hbit = (gt >> 4) & 1;
    const int rest = gt >> 5;
    const int d = ((rest & 31) << 4) + lane16;
    const int c = (rest >> 5) & (NC - 1);
    const int b = rest >> 12;
    const int s0 = hbit * SH;

    float4 ah[SH];
#pragma unroll
    for (int s = 0; s < SH; s++) {
        const int ai = d * SQ + s0 + s;
        ah[s] = make_float4(-0.5f * __expf(A_log[ai]), 0.5f * A_i[ai],
                             0.5f * A_j[ai],           0.5f * A_k[ai]);
    }

    const float4* __restrict__ u4 = (const float4*)u;
    const float4* __restrict__ B4 = (const float4*)Bin;

    const int t0 = c * CHUNKF;
    float4 Q[SH], H[SH];

    {   // peel first step: Q = q, H = q(x)Bu0 + Bu0
        const int td = b * LEN + t0;
        const float  dtv = dt[td * DQ + d];
        const float4 uu  = u4[td * DQ + d];
        const float  hdt = 0.5f * dtv;
        const float4 us  = make_float4(uu.x * hdt, uu.y * hdt, uu.z * hdt, uu.w * hdt);
#pragma unroll
        for (int s = 0; s < SH; s++) {
            const float4 Bq = B4[td * SQ + s0 + s];
            const float4 q  = step_q(dtv, ah[s]);
            const float4 Bu0 = qmul(Bq, us);
            Q[s] = q;
            H[s] = qmuladd(q, Bu0, Bu0);
        }
    }

#pragma unroll 2
    for (int i = 1; i < CHUNKF; i++) {
        const int td = b * LEN + t0 + i;
        const float  dtv = dt[td * DQ + d];
        const float4 uu  = u4[td * DQ + d];
        const float  hdt = 0.5f * dtv;
        const float4 us  = make_float4(uu.x * hdt, uu.y * hdt, uu.z * hdt, uu.w * hdt);
#pragma unroll
        for (int s = 0; s < SH; s++) {
            const float4 Bq = B4[td * SQ + s0 + s];
            const float4 q  = step_q(dtv, ah[s]);
            const float4 Bu0 = qmul(Bq, us);
            H[s] = qmuladd(q, add4(H[s], Bu0), Bu0);
            Q[s] = qmul(q, Q[s]);
        }
    }

#pragma unroll
    for (int s = 0; s < SH; s++) {
        const int idx = ((b * NC + c) * SQ + s0 + s) * DQ + d;
        g_Q[idx] = Q[s];
        g_H[idx] = H[s];
    }
}

// ---------------------------------------------------------------------------
// K2: warp-parallel affine scan. One warp per (b,s,d) chain; each lane owns
//     NCL=4 consecutive fine chunks. Local compose -> shfl_up scan -> replay.
// ---------------------------------------------------------------------------
__global__ void __launch_bounds__(256)
k_carry()
{
    const int gt = blockIdx.x * blockDim.x + threadIdx.x;
    const int lane = gt & 31;
    const int w = gt >> 5;                 // chain id in [0, BSZ*SQ*DQ)
    const int d = w & (DQ - 1);
    const int s = (w >> 9) & (SQ - 1);
    const int b = w >> 11;

    const int cstride = SQ * DQ;
    const int base = (b * NC * SQ + s) * DQ + d;
    const int c0 = lane * NCL;

    float4 Qc[NCL], Hc[NCL];
#pragma unroll
    for (int j = 0; j < NCL; j++) {
        const int idx = base + (c0 + j) * cstride;
        Qc[j] = g_Q[idx];
        Hc[j] = g_H[idx];
    }

    // Local inclusive composition over this lane's 4 chunks.
    float4 Qs = Qc[0], Hs = Hc[0];
#pragma unroll
    for (int j = 1; j < NCL; j++) {
        Hs = qmuladd(Qc[j], Hs, Hc[j]);
        Qs = qmul(Qc[j], Qs);
    }

    // Warp inclusive scan of the affine pair.
#pragma unroll
    for (int off = 1; off < 32; off <<= 1) {
        const float4 Qp = shfl_up4(Qs, off);
        const float4 Hp = shfl_up4(Hs, off);
        if (lane >= off) {
            Hs = qmuladd(Qs, Hp, Hs);   // pre-update Qs = current segment
            Qs = qmul(Qs, Qp);
        }
    }

    // Exclusive prefix = inclusive of lane-1 (identity at lane 0).
    float4 h = shfl_up4(Hs, 1);
    if (lane == 0) h = make_float4(0.f, 0.f, 0.f, 0.f);

    // Replay: emit carry-in for each owned chunk.
#pragma unroll
    for (int j = 0; j < NCL; j++) {
        const int idx = base + (c0 + j) * cstride;
        g_Hin[idx] = h;
        h = qmuladd(Qc[j], h, Hc[j]);
    }
}

// ---------------------------------------------------------------------------
// K3: per-(b, coarse-chunk, d) thread — all 4 s-lanes in-thread, recompute
//     with carry (Hin at fine chunk 2c), sum y in registers, float4 store.
// ---------------------------------------------------------------------------
__global__ void __launch_bounds__(256)
k_final(const float* __restrict__ u, const float* __restrict__ dt,
        const float* __restrict__ Bin, const float* __restrict__ Cin,
        const float* __restrict__ A_log, const float* __restrict__ A_i,
        const float* __restrict__ A_j,  const float* __restrict__ A_k,
        float* __restrict__ out)
{
    const int gt = blockIdx.x * blockDim.x + threadIdx.x;
    const int d = gt & (DQ - 1);
    const int c = (gt >> 9) & (NC3 - 1);
    const int b = gt >> 15;

    float4 ah[SQ];
#pragma unroll
    for (int s = 0; s < SQ; s++) {
        const int ai = d * SQ + s;
        ah[s] = make_float4(-0.5f * __expf(A_log[ai]), 0.5f * A_i[ai],
                             0.5f * A_j[ai],           0.5f * A_k[ai]);
    }

    float4 h[SQ];
#pragma unroll
    for (int s = 0; s < SQ; s++)
        h[s] = g_Hin[((b * NC + 2 * c) * SQ + s) * DQ + d];

    const float4* __restrict__ u4 = (const float4*)u;
    const float4* __restrict__ B4 = (const float4*)Bin;
    const float4* __restrict__ C4 = (const float4*)Cin;
    float4* __restrict__ o4 = (float4*)out;

    const int t0 = c * CHUNK3;
#pragma unroll 2
    for (int i = 0; i < CHUNK3; i++) {
        const int td = b * LEN + t0 + i;
        const float  dtv = dt[td * DQ + d];
        const float4 uu  = u4[td * DQ + d];
        const float  hdt = 0.5f * dtv;
        const float4 us  = make_float4(uu.x * hdt, uu.y * hdt, uu.z * hdt, uu.w * hdt);
        float4 y = make_float4(0.f, 0.f, 0.f, 0.f);
#pragma unroll
        for (int s = 0; s < SQ; s++) {
            const float4 Bq = B4[td * SQ + s];
            const float4 Cq = C4[td * SQ + s];
            const float4 q  = step_q(dtv, ah[s]);
            const float4 Bu0 = qmul(Bq, us);
            h[s] = qmuladd(q, add4(h[s], Bu0), Bu0);
            y = qmuladd(Cq, h[s], y);
        }
        o4[td * DQ + d] = y;
    }
}

// ---------------------------------------------------------------------------
// Launch
// ---------------------------------------------------------------------------
extern "C" void kernel_launch(void* const* d_in, const int* in_sizes, int n_in,
                              void* d_out, int out_size)
{
    const float* u     = (const float*)d_in[0];
    const float* dt    = (const float*)d_in[1];
    const float* Bin   = (const float*)d_in[2];
    const float* Cin   = (const float*)d_in[3];
    const float* A_log = (const float*)d_in[4];
    const float* A_i   = (const float*)d_in[5];
    const float* A_j   = (const float*)d_in[6];
    const float* A_k   = (const float*)d_in[7];
    float* out = (float*)d_out;

    const int k1_threads = BSZ * NC * DQ * 2;       // 262144
    const int k2_threads = BSZ * SQ * DQ * 32;      // 131072 (warp per chain)
    const int k3_threads = BSZ * NC3 * DQ;          // 65536

    k_summary<<<k1_threads / 256, 256>>>(u, dt, Bin, A_log, A_i, A_j, A_k);
    k_carry<<<k2_threads / 256, 256>>>();
    k_final<<<k3_threads / 256, 256>>>(u, dt, Bin, Cin, A_log, A_i, A_j, A_k, out);
}

// round 7
// speedup vs baseline: 1.5457x; 1.1200x over previous
#include <cuda_runtime.h>

// Problem constants (fixed by the reference)
#define BSZ    2
#define LEN    2048
#define DQ     512
#define SQ     4
#define SH     2                 // s-lanes per thread in K1
#define NC     128               // fine chunks along L (all kernels)
#define CHUNKF (LEN / NC)        // 16 steps per fine chunk
#define NCL    (NC / 32)         // fine chunks per lane in K2 warp scan (4)
#define EPSQ   1e-6f

// Scratch: chunk summaries and carries, laid out [b][chunk][s][d].
__device__ float4 g_Q  [BSZ * NC * SQ * DQ];
__device__ float4 g_H  [BSZ * NC * SQ * DQ];
__device__ float4 g_Hin[BSZ * NC * SQ * DQ];

// ---------------------------------------------------------------------------
// Quaternion helpers
// ---------------------------------------------------------------------------
__device__ __forceinline__ float4 qmuladd(const float4 a, const float4 b, const float4 c) {
    float4 r;
    r.x = fmaf(a.x, b.x, fmaf(-a.y, b.y, fmaf(-a.z, b.z, fmaf(-a.w, b.w, c.x))));
    r.y = fmaf(a.x, b.y, fmaf( a.y, b.x, fmaf( a.z, b.w, fmaf(-a.w, b.z, c.y))));
    r.z = fmaf(a.x, b.z, fmaf(-a.y, b.w, fmaf( a.z, b.x, fmaf( a.w, b.y, c.z))));
    r.w = fmaf(a.x, b.w, fmaf( a.y, b.z, fmaf(-a.z, b.y, fmaf( a.w, b.x, c.w))));
    return r;
}
__device__ __forceinline__ float4 qmul(const float4 a, const float4 b) {
    return qmuladd(a, b, make_float4(0.f, 0.f, 0.f, 0.f));
}
__device__ __forceinline__ float4 add4(const float4 a, const float4 b) {
    return make_float4(a.x + b.x, a.y + b.y, a.z + b.z, a.w + b.w);
}

// Approximate reciprocal (no Newton step): rel err ~2.4e-7, fine vs 1e-3 tol.
__device__ __forceinline__ float frcp(float x) {
    float r;
    asm("rcp.approx.f32 %0, %1;" : "=f"(r) : "f"(x));
    return r;
}

// Per-step transition quaternion (ah = 0.5*A):
//   n2 = (1-w_r)^2 + |w_v|^2 + eps ; r2 = 2/n2
//   q  = (omr*r2 - 1, w_i*r2, w_j*r2, w_k*r2)
// Injection identity:  us = u*(dt/2);  Bu0 = B (x) us
// Merged state update: h' = q (x) (h + Bu0) + Bu0
__device__ __forceinline__ float4 step_q(const float dtv, const float4 ah) {
    const float wr = dtv * ah.x, wi = dtv * ah.y, wj = dtv * ah.z, wk = dtv * ah.w;
    const float omr = 1.0f - wr;
    const float vve = fmaf(wi, wi, fmaf(wj, wj, fmaf(wk, wk, EPSQ)));
    const float n2  = fmaf(omr, omr, vve);
    const float r2  = frcp(n2) * 2.0f;
    return make_float4(fmaf(omr, r2, -1.0f), wi * r2, wj * r2, wk * r2);
}

__device__ __forceinline__ float4 shfl_up4(const float4 v, int off) {
    float4 r;
    r.x = __shfl_up_sync(0xffffffffu, v.x, off);
    r.y = __shfl_up_sync(0xffffffffu, v.y, off);
    r.z = __shfl_up_sync(0xffffffffu, v.z, off);
    r.w = __shfl_up_sync(0xffffffffu, v.w, off);
    return r;
}

// ---------------------------------------------------------------------------
// K1: per-(b, fine-chunk, d, s-half) thread — chunk transforms (Q, H).
//     minBlocks=4 forces regs <= 64 so 4 CTAs fit per SM (measured win).
// ---------------------------------------------------------------------------
__global__ void __launch_bounds__(256, 4)
k_summary(const float* __restrict__ u, const float* __restrict__ dt,
          const float* __restrict__ Bin,
          const float* __restrict__ A_log, const float* __restrict__ A_i,
          const float* __restrict__ A_j,  const float* __restrict__ A_k)
{
    const int gt = blockIdx.x * blockDim.x + threadIdx.x;
    const int lane16 = gt & 15;
    const int hbit = (gt >> 4) & 1;
    const int rest = gt >> 5;
    const int d = ((rest & 31) << 4) + lane16;
    const int c = (rest >> 5) & (NC - 1);
    const int b = rest >> 12;
    const int s0 = hbit * SH;

    float4 ah[SH];
#pragma unroll
    for (int s = 0; s < SH; s++) {
        const int ai = d * SQ + s0 + s;
        ah[s] = make_float4(-0.5f * __expf(A_log[ai]), 0.5f * A_i[ai],
                             0.5f * A_j[ai],           0.5f * A_k[ai]);
    }

    const float4* __restrict__ u4 = (const float4*)u;
    const float4* __restrict__ B4 = (const float4*)Bin;

    const int t0 = c * CHUNKF;
    float4 Q[SH], H[SH];

    {   // peel first step: Q = q, H = q(x)Bu0 + Bu0
        const int td = b * LEN + t0;
        const float  dtv = dt[td * DQ + d];
        const float4 uu  = u4[td * DQ + d];
        const float  hdt = 0.5f * dtv;
        const float4 us  = make_float4(uu.x * hdt, uu.y * hdt, uu.z * hdt, uu.w * hdt);
#pragma unroll
        for (int s = 0; s < SH; s++) {
            const float4 Bq = B4[td * SQ + s0 + s];
            const float4 q  = step_q(dtv, ah[s]);
            const float4 Bu0 = qmul(Bq, us);
            Q[s] = q;
            H[s] = qmuladd(q, Bu0, Bu0);
        }
    }

#pragma unroll 2
    for (int i = 1; i < CHUNKF; i++) {
        const int td = b * LEN + t0 + i;
        const float  dtv = dt[td * DQ + d];
        const float4 uu  = u4[td * DQ + d];
        const float  hdt = 0.5f * dtv;
        const float4 us  = make_float4(uu.x * hdt, uu.y * hdt, uu.z * hdt, uu.w * hdt);
#pragma unroll
        for (int s = 0; s < SH; s++) {
            const float4 Bq = B4[td * SQ + s0 + s];
            const float4 q  = step_q(dtv, ah[s]);
            const float4 Bu0 = qmul(Bq, us);
            H[s] = qmuladd(q, add4(H[s], Bu0), Bu0);
            Q[s] = qmul(q, Q[s]);
        }
    }

#pragma unroll
    for (int s = 0; s < SH; s++) {
        const int idx = ((b * NC + c) * SQ + s0 + s) * DQ + d;
        g_Q[idx] = Q[s];
        g_H[idx] = H[s];
    }
}

// ---------------------------------------------------------------------------
// K2: warp-parallel affine scan. One warp per (b,s,d) chain; each lane owns
//     NCL=4 consecutive fine chunks. Local compose -> shfl_up scan -> replay.
// ---------------------------------------------------------------------------
__global__ void __launch_bounds__(256)
k_carry()
{
    const int gt = blockIdx.x * blockDim.x + threadIdx.x;
    const int lane = gt & 31;
    const int w = gt >> 5;                 // chain id in [0, BSZ*SQ*DQ)
    const int d = w & (DQ - 1);
    const int s = (w >> 9) & (SQ - 1);
    const int b = w >> 11;

    const int cstride = SQ * DQ;
    const int base = (b * NC * SQ + s) * DQ + d;
    const int c0 = lane * NCL;

    float4 Qc[NCL], Hc[NCL];
#pragma unroll
    for (int j = 0; j < NCL; j++) {
        const int idx = base + (c0 + j) * cstride;
        Qc[j] = g_Q[idx];
        Hc[j] = g_H[idx];
    }

    // Local inclusive composition over this lane's 4 chunks.
    float4 Qs = Qc[0], Hs = Hc[0];
#pragma unroll
    for (int j = 1; j < NCL; j++) {
        Hs = qmuladd(Qc[j], Hs, Hc[j]);
        Qs = qmul(Qc[j], Qs);
    }

    // Warp inclusive scan of the affine pair.
#pragma unroll
    for (int off = 1; off < 32; off <<= 1) {
        const float4 Qp = shfl_up4(Qs, off);
        const float4 Hp = shfl_up4(Hs, off);
        if (lane >= off) {
            Hs = qmuladd(Qs, Hp, Hs);   // pre-update Qs = current segment
            Qs = qmul(Qs, Qp);
        }
    }

    // Exclusive prefix = inclusive of lane-1 (identity at lane 0).
    float4 h = shfl_up4(Hs, 1);
    if (lane == 0) h = make_float4(0.f, 0.f, 0.f, 0.f);

    // Replay: emit carry-in for each owned chunk.
#pragma unroll
    for (int j = 0; j < NCL; j++) {
        const int idx = base + (c0 + j) * cstride;
        g_Hin[idx] = h;
        h = qmuladd(Qc[j], h, Hc[j]);
    }
}

// ---------------------------------------------------------------------------
// K3: per-(b, fine-chunk, d) thread — all 4 s-lanes in-thread, CHUNK=16,
//     512 CTAs (measured-better shape). minBlocks=3 caps regs at 84.
// ---------------------------------------------------------------------------
__global__ void __launch_bounds__(256, 3)
k_final(const float* __restrict__ u, const float* __restrict__ dt,
        const float* __restrict__ Bin, const float* __restrict__ Cin,
        const float* __restrict__ A_log, const float* __restrict__ A_i,
        const float* __restrict__ A_j,  const float* __restrict__ A_k,
        float* __restrict__ out)
{
    const int gt = blockIdx.x * blockDim.x + threadIdx.x;
    const int d = gt & (DQ - 1);
    const int c = (gt >> 9) & (NC - 1);
    const int b = gt >> 16;

    float4 ah[SQ];
#pragma unroll
    for (int s = 0; s < SQ; s++) {
        const int ai = d * SQ + s;
        ah[s] = make_float4(-0.5f * __expf(A_log[ai]), 0.5f * A_i[ai],
                             0.5f * A_j[ai],           0.5f * A_k[ai]);
    }

    float4 h[SQ];
#pragma unroll
    for (int s = 0; s < SQ; s++)
        h[s] = g_Hin[((b * NC + c) * SQ + s) * DQ + d];

    const float4* __restrict__ u4 = (const float4*)u;
    const float4* __restrict__ B4 = (const float4*)Bin;
    const float4* __restrict__ C4 = (const float4*)Cin;
    float4* __restrict__ o4 = (float4*)out;

    const int t0 = c * CHUNKF;
#pragma unroll 2
    for (int i = 0; i < CHUNKF; i++) {
        const int td = b * LEN + t0 + i;
        const float  dtv = dt[td * DQ + d];
        const float4 uu  = u4[td * DQ + d];
        const float  hdt = 0.5f * dtv;
        const float4 us  = make_float4(uu.x * hdt, uu.y * hdt, uu.z * hdt, uu.w * hdt);
        float4 y = make_float4(0.f, 0.f, 0.f, 0.f);
#pragma unroll
        for (int s = 0; s < SQ; s++) {
            const float4 Bq = B4[td * SQ + s];
            const float4 Cq = C4[td * SQ + s];
            const float4 q  = step_q(dtv, ah[s]);
            const float4 Bu0 = qmul(Bq, us);
            h[s] = qmuladd(q, add4(h[s], Bu0), Bu0);
            y = qmuladd(Cq, h[s], y);
        }
        o4[td * DQ + d] = y;
    }
}

// ---------------------------------------------------------------------------
// Launch
// ---------------------------------------------------------------------------
extern "C" void kernel_launch(void* const* d_in, const int* in_sizes, int n_in,
                              void* d_out, int out_size)
{
    const float* u     = (const float*)d_in[0];
    const float* dt    = (const float*)d_in[1];
    const float* Bin   = (const float*)d_in[2];
    const float* Cin   = (const float*)d_in[3];
    const float* A_log = (const float*)d_in[4];
    const float* A_i   = (const float*)d_in[5];
    const float* A_j   = (const float*)d_in[6];
    const float* A_k   = (const float*)d_in[7];
    float* out = (float*)d_out;

    const int k1_threads = BSZ * NC * DQ * 2;       // 262144
    const int k2_threads = BSZ * SQ * DQ * 32;      // 131072 (warp per chain)
    const int k3_threads = BSZ * NC * DQ;           // 131072

    k_summary<<<k1_threads / 256, 256>>>(u, dt, Bin, A_log, A_i, A_j, A_k);
    k_carry<<<k2_threads / 256, 256>>>();
    k_final<<<k3_threads / 256, 256>>>(u, dt, Bin, Cin, A_log, A_i, A_j, A_k, out);
}

// round 8
// speedup vs baseline: 1.6816x; 1.0880x over previous
#include <cuda_runtime.h>

// Problem constants (fixed by the reference)
#define BSZ    2
#define LEN    2048
#define DQ     512
#define SQ     4
#define SH     2                 // s-lanes per thread (K1 and K3)
#define NC     128               // fine chunks along L (all kernels)
#define CHUNKF (LEN / NC)        // 16 steps per fine chunk
#define NCL    (NC / 32)         // fine chunks per lane in K2 warp scan (4)
#define EPSQ   1e-6f

// Scratch: chunk summaries and carries, laid out [b][chunk][s][d].
__device__ float4 g_Q  [BSZ * NC * SQ * DQ];
__device__ float4 g_H  [BSZ * NC * SQ * DQ];
__device__ float4 g_Hin[BSZ * NC * SQ * DQ];

// ---------------------------------------------------------------------------
// Quaternion helpers
// ---------------------------------------------------------------------------
__device__ __forceinline__ float4 qmuladd(const float4 a, const float4 b, const float4 c) {
    float4 r;
    r.x = fmaf(a.x, b.x, fmaf(-a.y, b.y, fmaf(-a.z, b.z, fmaf(-a.w, b.w, c.x))));
    r.y = fmaf(a.x, b.y, fmaf( a.y, b.x, fmaf( a.z, b.w, fmaf(-a.w, b.z, c.y))));
    r.z = fmaf(a.x, b.z, fmaf(-a.y, b.w, fmaf( a.z, b.x, fmaf( a.w, b.y, c.z))));
    r.w = fmaf(a.x, b.w, fmaf( a.y, b.z, fmaf(-a.z, b.y, fmaf( a.w, b.x, c.w))));
    return r;
}
__device__ __forceinline__ float4 qmul(const float4 a, const float4 b) {
    return qmuladd(a, b, make_float4(0.f, 0.f, 0.f, 0.f));
}
__device__ __forceinline__ float4 add4(const float4 a, const float4 b) {
    return make_float4(a.x + b.x, a.y + b.y, a.z + b.z, a.w + b.w);
}

// Approximate reciprocal (no Newton step): rel err ~2.4e-7, fine vs 1e-3 tol.
__device__ __forceinline__ float frcp(float x) {
    float r;
    asm("rcp.approx.f32 %0, %1;" : "=f"(r) : "f"(x));
    return r;
}

// Per-step transition quaternion (ah = 0.5*A):
//   n2 = (1-w_r)^2 + |w_v|^2 + eps ; r2 = 2/n2
//   q  = (omr*r2 - 1, w_i*r2, w_j*r2, w_k*r2)
// Injection identity:  us = u*(dt/2);  Bu0 = B (x) us
// Merged state update: h' = q (x) (h + Bu0) + Bu0
__device__ __forceinline__ float4 step_q(const float dtv, const float4 ah) {
    const float wr = dtv * ah.x, wi = dtv * ah.y, wj = dtv * ah.z, wk = dtv * ah.w;
    const float omr = 1.0f - wr;
    const float vve = fmaf(wi, wi, fmaf(wj, wj, fmaf(wk, wk, EPSQ)));
    const float n2  = fmaf(omr, omr, vve);
    const float r2  = frcp(n2) * 2.0f;
    return make_float4(fmaf(omr, r2, -1.0f), wi * r2, wj * r2, wk * r2);
}

__device__ __forceinline__ float4 shfl_up4(const float4 v, int off) {
    float4 r;
    r.x = __shfl_up_sync(0xffffffffu, v.x, off);
    r.y = __shfl_up_sync(0xffffffffu, v.y, off);
    r.z = __shfl_up_sync(0xffffffffu, v.z, off);
    r.w = __shfl_up_sync(0xffffffffu, v.w, off);
    return r;
}

// ---------------------------------------------------------------------------
// K1: per-(b, fine-chunk, d, s-half) thread — chunk transforms (Q, H).
//     minBlocks=4 forces regs <= 64 so 4 CTAs fit per SM (measured win).
// ---------------------------------------------------------------------------
__global__ void __launch_bounds__(256, 4)
k_summary(const float* __restrict__ u, const float* __restrict__ dt,
          const float* __restrict__ Bin,
          const float* __restrict__ A_log, const float* __restrict__ A_i,
          const float* __restrict__ A_j,  const float* __restrict__ A_k)
{
    const int gt = blockIdx.x * blockDim.x + threadIdx.x;
    const int lane16 = gt & 15;
    const int hbit = (gt >> 4) & 1;
    const int rest = gt >> 5;
    const int d = ((rest & 31) << 4) + lane16;
    const int c = (rest >> 5) & (NC - 1);
    const int b = rest >> 12;
    const int s0 = hbit * SH;

    float4 ah[SH];
#pragma unroll
    for (int s = 0; s < SH; s++) {
        const int ai = d * SQ + s0 + s;
        ah[s] = make_float4(-0.5f * __expf(A_log[ai]), 0.5f * A_i[ai],
                             0.5f * A_j[ai],           0.5f * A_k[ai]);
    }

    const float4* __restrict__ u4 = (const float4*)u;
    const float4* __restrict__ B4 = (const float4*)Bin;

    const int t0 = c * CHUNKF;
    float4 Q[SH], H[SH];

    {   // peel first step: Q = q, H = q(x)Bu0 + Bu0
        const int td = b * LEN + t0;
        const float  dtv = dt[td * DQ + d];
        const float4 uu  = u4[td * DQ + d];
        const float  hdt = 0.5f * dtv;
        const float4 us  = make_float4(uu.x * hdt, uu.y * hdt, uu.z * hdt, uu.w * hdt);
#pragma unroll
        for (int s = 0; s < SH; s++) {
            const float4 Bq = B4[td * SQ + s0 + s];
            const float4 q  = step_q(dtv, ah[s]);
            const float4 Bu0 = qmul(Bq, us);
            Q[s] = q;
            H[s] = qmuladd(q, Bu0, Bu0);
        }
    }

#pragma unroll 2
    for (int i = 1; i < CHUNKF; i++) {
        const int td = b * LEN + t0 + i;
        const float  dtv = dt[td * DQ + d];
        const float4 uu  = u4[td * DQ + d];
        const float  hdt = 0.5f * dtv;
        const float4 us  = make_float4(uu.x * hdt, uu.y * hdt, uu.z * hdt, uu.w * hdt);
#pragma unroll
        for (int s = 0; s < SH; s++) {
            const float4 Bq = B4[td * SQ + s0 + s];
            const float4 q  = step_q(dtv, ah[s]);
            const float4 Bu0 = qmul(Bq, us);
            H[s] = qmuladd(q, add4(H[s], Bu0), Bu0);
            Q[s] = qmul(q, Q[s]);
        }
    }

#pragma unroll
    for (int s = 0; s < SH; s++) {
        const int idx = ((b * NC + c) * SQ + s0 + s) * DQ + d;
        g_Q[idx] = Q[s];
        g_H[idx] = H[s];
    }
}

// ---------------------------------------------------------------------------
// K2: warp-parallel affine scan. One warp per (b,s,d) chain; each lane owns
//     NCL=4 consecutive fine chunks. Local compose -> shfl_up scan -> replay.
// ---------------------------------------------------------------------------
__global__ void __launch_bounds__(256)
k_carry()
{
    const int gt = blockIdx.x * blockDim.x + threadIdx.x;
    const int lane = gt & 31;
    const int w = gt >> 5;                 // chain id in [0, BSZ*SQ*DQ)
    const int d = w & (DQ - 1);
    const int s = (w >> 9) & (SQ - 1);
    const int b = w >> 11;

    const int cstride = SQ * DQ;
    const int base = (b * NC * SQ + s) * DQ + d;
    const int c0 = lane * NCL;

    float4 Qc[NCL], Hc[NCL];
#pragma unroll
    for (int j = 0; j < NCL; j++) {
        const int idx = base + (c0 + j) * cstride;
        Qc[j] = g_Q[idx];
        Hc[j] = g_H[idx];
    }

    // Local inclusive composition over this lane's 4 chunks.
    float4 Qs = Qc[0], Hs = Hc[0];
#pragma unroll
    for (int j = 1; j < NCL; j++) {
        Hs = qmuladd(Qc[j], Hs, Hc[j]);
        Qs = qmul(Qc[j], Qs);
    }

    // Warp inclusive scan of the affine pair.
#pragma unroll
    for (int off = 1; off < 32; off <<= 1) {
        const float4 Qp = shfl_up4(Qs, off);
        const float4 Hp = shfl_up4(Hs, off);
        if (lane >= off) {
            Hs = qmuladd(Qs, Hp, Hs);   // pre-update Qs = current segment
            Qs = qmul(Qs, Qp);
        }
    }

    // Exclusive prefix = inclusive of lane-1 (identity at lane 0).
    float4 h = shfl_up4(Hs, 1);
    if (lane == 0) h = make_float4(0.f, 0.f, 0.f, 0.f);

    // Replay: emit carry-in for each owned chunk.
#pragma unroll
    for (int j = 0; j < NCL; j++) {
        const int idx = base + (c0 + j) * cstride;
        g_Hin[idx] = h;
        h = qmuladd(Qc[j], h, Hc[j]);
    }
}

// ---------------------------------------------------------------------------
// K3: per-(b, fine-chunk, d, s-half) thread — recompute with carry, emit y.
//     SH=2 split (same decomp as K1): ~55 regs -> 4 CTAs/SM, 1024 CTAs.
//     Pair-sum over s-halves via shfl_xor(16); hbit==0 lanes store float4.
// ---------------------------------------------------------------------------
__global__ void __launch_bounds__(256, 4)
k_final(const float* __restrict__ u, const float* __restrict__ dt,
        const float* __restrict__ Bin, const float* __restrict__ Cin,
        const float* __restrict__ A_log, const float* __restrict__ A_i,
        const float* __restrict__ A_j,  const float* __restrict__ A_k,
        float* __restrict__ out)
{
    const int gt = blockIdx.x * blockDim.x + threadIdx.x;
    const int lane16 = gt & 15;
    const int hbit = (gt >> 4) & 1;
    const int rest = gt >> 5;
    const int d = ((rest & 31) << 4) + lane16;
    const int c = (rest >> 5) & (NC - 1);
    const int b = rest >> 12;
    const int s0 = hbit * SH;

    float4 ah[SH];
#pragma unroll
    for (int s = 0; s < SH; s++) {
        const int ai = d * SQ + s0 + s;
        ah[s] = make_float4(-0.5f * __expf(A_log[ai]), 0.5f * A_i[ai],
                             0.5f * A_j[ai],           0.5f * A_k[ai]);
    }

    float4 h[SH];
#pragma unroll
    for (int s = 0; s < SH; s++)
        h[s] = g_Hin[((b * NC + c) * SQ + s0 + s) * DQ + d];

    const float4* __restrict__ u4 = (const float4*)u;
    const float4* __restrict__ B4 = (const float4*)Bin;
    const float4* __restrict__ C4 = (const float4*)Cin;
    float4* __restrict__ o4 = (float4*)out;

    const int t0 = c * CHUNKF;
#pragma unroll 2
    for (int i = 0; i < CHUNKF; i++) {
        const int td = b * LEN + t0 + i;
        const float  dtv = dt[td * DQ + d];
        const float4 uu  = u4[td * DQ + d];
        const float  hdt = 0.5f * dtv;
        const float4 us  = make_float4(uu.x * hdt, uu.y * hdt, uu.z * hdt, uu.w * hdt);
        float4 y = make_float4(0.f, 0.f, 0.f, 0.f);
#pragma unroll
        for (int s = 0; s < SH; s++) {
            const float4 Bq = B4[td * SQ + s0 + s];
            const float4 Cq = C4[td * SQ + s0 + s];
            const float4 q  = step_q(dtv, ah[s]);
            const float4 Bu0 = qmul(Bq, us);
            h[s] = qmuladd(q, add4(h[s], Bu0), Bu0);
            y = qmuladd(Cq, h[s], y);
        }
        // Pair-reduce across s-halves (lane bit 4).
        y.x += __shfl_xor_sync(0xffffffffu, y.x, 16);
        y.y += __shfl_xor_sync(0xffffffffu, y.y, 16);
        y.z += __shfl_xor_sync(0xffffffffu, y.z, 16);
        y.w += __shfl_xor_sync(0xffffffffu, y.w, 16);
        if (hbit == 0)
            o4[td * DQ + d] = y;
    }
}

// ---------------------------------------------------------------------------
// Launch
// ---------------------------------------------------------------------------
extern "C" void kernel_launch(void* const* d_in, const int* in_sizes, int n_in,
                              void* d_out, int out_size)
{
    const float* u     = (const float*)d_in[0];
    const float* dt    = (const float*)d_in[1];
    const float* Bin   = (const float*)d_in[2];
    const float* Cin   = (const float*)d_in[3];
    const float* A_log = (const float*)d_in[4];
    const float* A_i   = (const float*)d_in[5];
    const float* A_j   = (const float*)d_in[6];
    const float* A_k   = (const float*)d_in[7];
    float* out = (float*)d_out;

    const int k1_threads = BSZ * NC * DQ * 2;       // 262144
    const int k2_threads = BSZ * SQ * DQ * 32;      // 131072 (warp per chain)
    const int k3_threads = BSZ * NC * DQ * 2;       // 262144

    k_summary<<<k1_threads / 256, 256>>>(u, dt, Bin, A_log, A_i, A_j, A_k);
    k_carry<<<k2_threads / 256, 256>>>();
    k_final<<<k3_threads / 256, 256>>>(u, dt, Bin, Cin, A_log, A_i, A_j, A_k, out);
}